// round 5
// baseline (speedup 1.0000x reference)
#include <cuda_runtime.h>

#define BS     8192
#define H      256
#define KC     64
#define RPB    32          // rows per block in Q kernel
#define CT_STRIDE 65       // 64 + 1 pad  -> conflict-free (stride % 32 == 1)
#define ZT_STRIDE 33       // 32 + 1 pad  -> conflict-free

// Per-block partial column sums of normalized Q (deterministic tree, no atomics)
__device__ float g_colpart[(BS / RPB) * KC];

// ---------------------------------------------------------------------------
// Kernel 1: compute Q (row-normalized student-t) + per-block column partials
// Block: 256 threads, tile = 32 rows x 64 clusters, per-thread 2x4 register tile
// ---------------------------------------------------------------------------
__global__ __launch_bounds__(256, 2)
void qk_kernel(const float* __restrict__ z, const float* __restrict__ cent,
               float* __restrict__ Qout)
{
    extern __shared__ float smem[];
    float* cT     = smem;                        // [256][65]  cT[k][j]
    float* zT     = cT + H * CT_STRIDE;          // [256][33]  zT[k][r]
    float* cn     = zT + H * ZT_STRIDE;          // [64]  ||c_j||^2
    float* zz     = cn + KC;                     // [32]  ||z_r||^2
    float* colred = zz + RPB;                    // [16][64]
    float* npart  = colred + 16 * KC;            // [192]

    const int tid  = threadIdx.x;
    const int row0 = blockIdx.x * RPB;

    // --- stage centroids transposed (coalesced LDG, conflict-free STS) ---
    #pragma unroll
    for (int i = tid; i < KC * H; i += 256) {
        int j = i >> 8, k = i & 255;
        cT[k * CT_STRIDE + j] = cent[i];
    }
    // --- stage z tile transposed ---
    #pragma unroll
    for (int i = tid; i < RPB * H; i += 256) {
        int r = i >> 8, k = i & 255;
        zT[k * ZT_STRIDE + r] = z[(size_t)(row0 + r) * H + k];
    }
    __syncthreads();

    // --- cooperative norms: 96 jobs (64 centroids + 32 rows) x 2 k-halves ---
    if (tid < 192) {
        const int job  = (tid < 96) ? tid : tid - 96;
        const int half = (tid < 96) ? 0 : 1;
        float s = 0.f;
        if (job < KC) {
            const float* p = cT + job + half * 128 * CT_STRIDE;
            #pragma unroll 8
            for (int k = 0; k < 128; k++) { float v = p[k * CT_STRIDE]; s = fmaf(v, v, s); }
        } else {
            const float* p = zT + (job - KC) + half * 128 * ZT_STRIDE;
            #pragma unroll 8
            for (int k = 0; k < 128; k++) { float v = p[k * ZT_STRIDE]; s = fmaf(v, v, s); }
        }
        npart[half * 96 + job] = s;
    }
    __syncthreads();
    if (tid < 96) {
        float s = npart[tid] + npart[96 + tid];
        if (tid < KC) cn[tid] = s; else zz[tid - KC] = s;
    }
    __syncthreads();

    // --- main dot-product loop: 2 rows x 4 clusters per thread ---
    const int tx = tid & 15;          // cluster group (4 clusters)
    const int ty = tid >> 4;          // row group (2 rows)
    const float* cp = cT + tx * 4;
    const float* zp = zT + ty * 2;

    float a00 = 0.f, a01 = 0.f, a02 = 0.f, a03 = 0.f;
    float a10 = 0.f, a11 = 0.f, a12 = 0.f, a13 = 0.f;

    #pragma unroll 4
    for (int k = 0; k < H; k++) {
        const float z0 = zp[k * ZT_STRIDE];
        const float z1 = zp[k * ZT_STRIDE + 1];
        const float c0 = cp[k * CT_STRIDE];
        const float c1 = cp[k * CT_STRIDE + 1];
        const float c2 = cp[k * CT_STRIDE + 2];
        const float c3 = cp[k * CT_STRIDE + 3];
        a00 = fmaf(z0, c0, a00);  a01 = fmaf(z0, c1, a01);
        a02 = fmaf(z0, c2, a02);  a03 = fmaf(z0, c3, a03);
        a10 = fmaf(z1, c0, a10);  a11 = fmaf(z1, c1, a11);
        a12 = fmaf(z1, c2, a12);  a13 = fmaf(z1, c3, a13);
    }

    const float cn0 = cn[tx * 4 + 0], cn1 = cn[tx * 4 + 1];
    const float cn2 = cn[tx * 4 + 2], cn3 = cn[tx * 4 + 3];
    const float zz0 = zz[ty * 2 + 0], zz1 = zz[ty * 2 + 1];

    // q_unnorm = (1 + dist)^-1
    float q00 = 1.f / (1.f + sqrtf(fmaxf(zz0 + cn0 - 2.f * a00, 0.f)));
    float q01 = 1.f / (1.f + sqrtf(fmaxf(zz0 + cn1 - 2.f * a01, 0.f)));
    float q02 = 1.f / (1.f + sqrtf(fmaxf(zz0 + cn2 - 2.f * a02, 0.f)));
    float q03 = 1.f / (1.f + sqrtf(fmaxf(zz0 + cn3 - 2.f * a03, 0.f)));
    float q10 = 1.f / (1.f + sqrtf(fmaxf(zz1 + cn0 - 2.f * a10, 0.f)));
    float q11 = 1.f / (1.f + sqrtf(fmaxf(zz1 + cn1 - 2.f * a11, 0.f)));
    float q12 = 1.f / (1.f + sqrtf(fmaxf(zz1 + cn2 - 2.f * a12, 0.f)));
    float q13 = 1.f / (1.f + sqrtf(fmaxf(zz1 + cn3 - 2.f * a13, 0.f)));

    // row sums across the 16 tx lanes (within one 16-lane half of the warp)
    float rs0 = q00 + q01 + q02 + q03;
    float rs1 = q10 + q11 + q12 + q13;
    #pragma unroll
    for (int m = 1; m < 16; m <<= 1) {
        rs0 += __shfl_xor_sync(0xffffffffu, rs0, m);
        rs1 += __shfl_xor_sync(0xffffffffu, rs1, m);
    }
    const float i0 = 1.f / rs0;
    const float i1 = 1.f / rs1;
    q00 *= i0; q01 *= i0; q02 *= i0; q03 *= i0;
    q10 *= i1; q11 *= i1; q12 *= i1; q13 *= i1;

    const int r0g = row0 + ty * 2;
    *(float4*)(Qout + (size_t)r0g * KC + tx * 4)       = make_float4(q00, q01, q02, q03);
    *(float4*)(Qout + (size_t)(r0g + 1) * KC + tx * 4) = make_float4(q10, q11, q12, q13);

    // per-block column partials (deterministic smem tree)
    *(float4*)(colred + ty * KC + tx * 4) =
        make_float4(q00 + q10, q01 + q11, q02 + q12, q03 + q13);
    __syncthreads();
    if (tid < KC) {
        float s = 0.f;
        #pragma unroll
        for (int t = 0; t < 16; t++) s += colred[t * KC + tid];
        g_colpart[blockIdx.x * KC + tid] = s;
    }
}

// ---------------------------------------------------------------------------
// Kernel 2: reduce column partials (redundantly per block, deterministic),
// then P = rownorm( Q^2 / colsum(Q) ).  64 rows per block, 1 warp per 8 rows.
// ---------------------------------------------------------------------------
__global__ __launch_bounds__(256)
void p_kernel(const float* __restrict__ Qin, float* __restrict__ Pout)
{
    __shared__ float csi[KC];
    __shared__ float part[4][KC];

    const int tid = threadIdx.x;
    const int j   = tid & 63;
    const int pr  = tid >> 6;

    float s = 0.f;
    #pragma unroll 8
    for (int b = pr; b < (BS / RPB); b += 4) s += g_colpart[b * KC + j];
    part[pr][j] = s;
    __syncthreads();
    if (tid < KC)
        csi[tid] = 1.0f / (part[0][tid] + part[1][tid] + part[2][tid] + part[3][tid]);
    __syncthreads();

    const int warp = tid >> 5, lane = tid & 31;
    const float w0 = csi[lane * 2];
    const float w1 = csi[lane * 2 + 1];
    const int rowbase = blockIdx.x * 64 + warp * 8;

    #pragma unroll
    for (int rr = 0; rr < 8; rr++) {
        const int row = rowbase + rr;
        const float2 q = *(const float2*)(Qin + (size_t)row * KC + lane * 2);
        const float p0 = q.x * q.x * w0;
        const float p1 = q.y * q.y * w1;
        float rs = p0 + p1;
        #pragma unroll
        for (int m = 1; m < 32; m <<= 1) rs += __shfl_xor_sync(0xffffffffu, rs, m);
        const float inv = 1.0f / rs;
        float2 o; o.x = p0 * inv; o.y = p1 * inv;
        *(float2*)(Pout + (size_t)row * KC + lane * 2) = o;
    }
}

// ---------------------------------------------------------------------------
extern "C" void kernel_launch(void* const* d_in, const int* in_sizes, int n_in,
                              void* d_out, int out_size)
{
    const float* z    = (const float*)d_in[0];   // (8192, 256)
    const float* cent = (const float*)d_in[1];   // (64, 256)
    float* Q = (float*)d_out;                    // (8192, 64)
    float* P = Q + (size_t)BS * KC;              // (8192, 64)

    const size_t smem_bytes =
        (size_t)(H * CT_STRIDE + H * ZT_STRIDE + KC + RPB + 16 * KC + 192) * sizeof(float);

    cudaFuncSetAttribute(qk_kernel, cudaFuncAttributeMaxDynamicSharedMemorySize,
                         (int)smem_bytes);

    qk_kernel<<<BS / RPB, 256, smem_bytes>>>(z, cent, Q);
    p_kernel<<<BS / 64, 256>>>(Q, P);
}

// round 6
// speedup vs baseline: 1.3253x; 1.3253x over previous
#include <cuda_runtime.h>

#define BS   8192
#define H    256
#define KC   64
#define RPB  64                 // rows per block in Q kernel
#define NBLK (BS / RPB)         // 128 blocks
#define SC   68                 // cT row stride (floats): 16B-aligned, conflict-free reads
#define SZ   72                 // zT row stride (floats): 16B-aligned, conflict-free reads

// Per-block partial column sums of normalized Q, and inverse colsums
__device__ float g_colpart[NBLK * KC];
__device__ float g_csi[KC];

// ---------------------------------------------------------------------------
// Kernel 1: Q = rownorm( 1/(1+dist) ), plus per-block column partials of Q.
// Block: 256 threads, tile 64 rows x 64 clusters, per-thread 4x4 register tile.
// Main loop: 2x LDS.128 + 16 FFMA per k per thread  ->  FMA-pipe bound.
// ---------------------------------------------------------------------------
__global__ __launch_bounds__(256, 1)
void qk_kernel(const float* __restrict__ z, const float* __restrict__ cent,
               float* __restrict__ Qout)
{
    extern __shared__ float smem[];
    float* cT     = smem;                        // [256][SC]  cT[k][j]
    float* zT     = cT + H * SC;                 // [256][SZ]  zT[k][r]
    float* cnp    = zT + H * SZ;                 // [4][64] centroid-norm partials
    float* znp    = cnp + 4 * KC;                // [4][64] z-norm partials
    float* cn     = znp + 4 * RPB;               // [64]  ||c_j||^2
    float* zz     = cn + KC;                     // [64]  ||z_r||^2
    float* colred = zz + RPB;                    // [16][64]

    const int tid  = threadIdx.x;
    const int row0 = blockIdx.x * RPB;

    // ---- staging: transpose z tile and centroids into smem, fuse norms ----
    // mapping: r/j = tid&63 (fixed per thread), kg = (tid>>6) + 4*pass
    {
        const int rr  = tid & 63;
        const int kg0 = tid >> 6;

        float zsq = 0.f;
        #pragma unroll
        for (int p = 0; p < 16; p++) {
            const int kg = kg0 + p * 4;
            const float4 v = *(const float4*)(z + (size_t)(row0 + rr) * H + kg * 4);
            zT[(kg * 4 + 0) * SZ + rr] = v.x;
            zT[(kg * 4 + 1) * SZ + rr] = v.y;
            zT[(kg * 4 + 2) * SZ + rr] = v.z;
            zT[(kg * 4 + 3) * SZ + rr] = v.w;
            zsq = fmaf(v.x, v.x, zsq); zsq = fmaf(v.y, v.y, zsq);
            zsq = fmaf(v.z, v.z, zsq); zsq = fmaf(v.w, v.w, zsq);
        }
        znp[kg0 * 64 + rr] = zsq;

        float csq = 0.f;
        #pragma unroll
        for (int p = 0; p < 16; p++) {
            const int kg = kg0 + p * 4;
            const float4 v = *(const float4*)(cent + (size_t)rr * H + kg * 4);
            cT[(kg * 4 + 0) * SC + rr] = v.x;
            cT[(kg * 4 + 1) * SC + rr] = v.y;
            cT[(kg * 4 + 2) * SC + rr] = v.z;
            cT[(kg * 4 + 3) * SC + rr] = v.w;
            csq = fmaf(v.x, v.x, csq); csq = fmaf(v.y, v.y, csq);
            csq = fmaf(v.z, v.z, csq); csq = fmaf(v.w, v.w, csq);
        }
        cnp[kg0 * 64 + rr] = csq;
    }
    __syncthreads();

    if (tid < 64)
        cn[tid] = cnp[0 * 64 + tid] + cnp[1 * 64 + tid] + cnp[2 * 64 + tid] + cnp[3 * 64 + tid];
    else if (tid < 128) {
        const int r = tid - 64;
        zz[r] = znp[0 * 64 + r] + znp[1 * 64 + r] + znp[2 * 64 + r] + znp[3 * 64 + r];
    }
    __syncthreads();

    // ---- main dot-product loop: 4 rows x 4 clusters per thread ----
    const int tx = tid & 15;     // cluster group: cols 4*tx..4*tx+3
    const int ty = tid >> 4;     // row group:     rows 4*ty..4*ty+3
    const float* cp = cT + 4 * tx;
    const float* zp = zT + 4 * ty;

    float a[4][4];
    #pragma unroll
    for (int i = 0; i < 4; i++)
        #pragma unroll
        for (int j = 0; j < 4; j++) a[i][j] = 0.f;

    #pragma unroll 8
    for (int k = 0; k < H; k++) {
        const float4 cv = *(const float4*)(cp + k * SC);
        const float4 zv = *(const float4*)(zp + k * SZ);
        a[0][0] = fmaf(zv.x, cv.x, a[0][0]); a[0][1] = fmaf(zv.x, cv.y, a[0][1]);
        a[0][2] = fmaf(zv.x, cv.z, a[0][2]); a[0][3] = fmaf(zv.x, cv.w, a[0][3]);
        a[1][0] = fmaf(zv.y, cv.x, a[1][0]); a[1][1] = fmaf(zv.y, cv.y, a[1][1]);
        a[1][2] = fmaf(zv.y, cv.z, a[1][2]); a[1][3] = fmaf(zv.y, cv.w, a[1][3]);
        a[2][0] = fmaf(zv.z, cv.x, a[2][0]); a[2][1] = fmaf(zv.z, cv.y, a[2][1]);
        a[2][2] = fmaf(zv.z, cv.z, a[2][2]); a[2][3] = fmaf(zv.z, cv.w, a[2][3]);
        a[3][0] = fmaf(zv.w, cv.x, a[3][0]); a[3][1] = fmaf(zv.w, cv.y, a[3][1]);
        a[3][2] = fmaf(zv.w, cv.z, a[3][2]); a[3][3] = fmaf(zv.w, cv.w, a[3][3]);
    }

    // ---- epilogue: q = 1/(1 + dist), row-normalize ----
    float cn4[4], zz4[4];
    #pragma unroll
    for (int j = 0; j < 4; j++) cn4[j] = cn[4 * tx + j];
    #pragma unroll
    for (int i = 0; i < 4; i++) zz4[i] = zz[4 * ty + i];

    #pragma unroll
    for (int i = 0; i < 4; i++)
        #pragma unroll
        for (int j = 0; j < 4; j++) {
            const float d2 = fmaxf(zz4[i] + cn4[j] - 2.f * a[i][j], 0.f);
            a[i][j] = 1.f / (1.f + sqrtf(d2));
        }

    float rs[4];
    #pragma unroll
    for (int i = 0; i < 4; i++)
        rs[i] = a[i][0] + a[i][1] + a[i][2] + a[i][3];
    #pragma unroll
    for (int m = 1; m < 16; m <<= 1) {
        #pragma unroll
        for (int i = 0; i < 4; i++)
            rs[i] += __shfl_xor_sync(0xffffffffu, rs[i], m);
    }
    #pragma unroll
    for (int i = 0; i < 4; i++) {
        const float inv = 1.f / rs[i];
        a[i][0] *= inv; a[i][1] *= inv; a[i][2] *= inv; a[i][3] *= inv;
    }

    // Q writes (coalesced: 16 tx lanes cover a full 256B row)
    #pragma unroll
    for (int i = 0; i < 4; i++) {
        const int row = row0 + 4 * ty + i;
        *(float4*)(Qout + (size_t)row * KC + 4 * tx) =
            make_float4(a[i][0], a[i][1], a[i][2], a[i][3]);
    }

    // per-block column partials of normalized Q (deterministic smem tree)
    *(float4*)(colred + ty * KC + 4 * tx) =
        make_float4(a[0][0] + a[1][0] + a[2][0] + a[3][0],
                    a[0][1] + a[1][1] + a[2][1] + a[3][1],
                    a[0][2] + a[1][2] + a[2][2] + a[3][2],
                    a[0][3] + a[1][3] + a[2][3] + a[3][3]);
    __syncthreads();
    if (tid < KC) {
        float s = 0.f;
        #pragma unroll
        for (int t = 0; t < 16; t++) s += colred[t * KC + tid];
        g_colpart[blockIdx.x * KC + tid] = s;
    }
}

// ---------------------------------------------------------------------------
// Kernel 2: reduce column partials -> inverse column sums (1 block, tiny)
// ---------------------------------------------------------------------------
__global__ __launch_bounds__(256)
void colsum_kernel()
{
    __shared__ float part[4][KC];
    const int tid = threadIdx.x;
    const int j   = tid & 63;
    const int pr  = tid >> 6;

    float s = 0.f;
    #pragma unroll 8
    for (int b = pr; b < NBLK; b += 4) s += g_colpart[b * KC + j];
    part[pr][j] = s;
    __syncthreads();
    if (tid < KC)
        g_csi[tid] = 1.0f / (part[0][tid] + part[1][tid] + part[2][tid] + part[3][tid]);
}

// ---------------------------------------------------------------------------
// Kernel 3: P = rownorm( Q^2 * csi ).  1 row per warp-iteration, 32 rows/block,
// 256 blocks -> full occupancy, coalesced float2.
// ---------------------------------------------------------------------------
__global__ __launch_bounds__(256)
void p_kernel(const float* __restrict__ Qin, float* __restrict__ Pout)
{
    __shared__ float csi_s[KC];
    const int tid = threadIdx.x;
    if (tid < KC) csi_s[tid] = g_csi[tid];
    __syncthreads();

    const int lane = tid & 31, warp = tid >> 5;
    const float w0 = csi_s[2 * lane];
    const float w1 = csi_s[2 * lane + 1];
    const int rowbase = blockIdx.x * 32 + warp * 4;

    #pragma unroll
    for (int rr = 0; rr < 4; rr++) {
        const int row = rowbase + rr;
        const float2 q = *(const float2*)(Qin + (size_t)row * KC + 2 * lane);
        const float p0 = q.x * q.x * w0;
        const float p1 = q.y * q.y * w1;
        float rs = p0 + p1;
        #pragma unroll
        for (int m = 1; m < 32; m <<= 1) rs += __shfl_xor_sync(0xffffffffu, rs, m);
        const float inv = 1.0f / rs;
        float2 o; o.x = p0 * inv; o.y = p1 * inv;
        *(float2*)(Pout + (size_t)row * KC + 2 * lane) = o;
    }
}

// ---------------------------------------------------------------------------
extern "C" void kernel_launch(void* const* d_in, const int* in_sizes, int n_in,
                              void* d_out, int out_size)
{
    const float* z    = (const float*)d_in[0];   // (8192, 256)
    const float* cent = (const float*)d_in[1];   // (64, 256)
    float* Q = (float*)d_out;                    // (8192, 64)
    float* P = Q + (size_t)BS * KC;              // (8192, 64)

    const size_t smem_bytes =
        (size_t)(H * SC + H * SZ + 4 * KC + 4 * RPB + KC + RPB + 16 * KC) * sizeof(float);

    cudaFuncSetAttribute(qk_kernel, cudaFuncAttributeMaxDynamicSharedMemorySize,
                         (int)smem_bytes);

    qk_kernel<<<NBLK, 256, smem_bytes>>>(z, cent, Q);
    colsum_kernel<<<1, 256>>>();
    p_kernel<<<BS / 32, 256>>>(Q, P);
}